// round 1
// baseline (speedup 1.0000x reference)
#include <cuda_runtime.h>
#include <cuda_bf16.h>

#define N_NODES 50000
#define N_EDGES 800000
#define DIM_IN  128
#define DIM_OUT 64
#define HEADS   4
#define NEG_SLOPE 0.2f
#define H_COLS  (HEADS * DIM_OUT)   // 256

// ---------------- scratch (device globals; no allocation allowed) ----------
__device__ __align__(16) float g_H[N_NODES * H_COLS];     // 51.2 MB, h = x @ W
__device__ __align__(16) float g_si[N_NODES * HEADS];
__device__ __align__(16) float g_sj[N_NODES * HEADS];
__device__ int g_counts[N_NODES];
__device__ int g_row_ptr[N_NODES + 1];
__device__ int g_cursor[N_NODES];
__device__ int g_dst_sorted[N_EDGES];

// ---------------- GEMM: h[n][h][o] = sum_d x[n][d] * W[h][d][o] ------------
// BM=64 rows, BN=64 (= one head), BK=32, 256 threads, 4x4 microtile.
__global__ void __launch_bounds__(256) gemm_kernel(const float* __restrict__ X,
                                                   const float* __restrict__ W) {
    __shared__ float As[64][36];   // padded: stride 36 -> 4-bank row shift
    __shared__ float Bs[32][64];

    const int h    = blockIdx.y;
    const int row0 = blockIdx.x * 64;
    const int tid  = threadIdx.x;
    const float* Wh = W + h * DIM_IN * DIM_OUT;

    const int tx = tid & 15;
    const int ty = tid >> 4;

    float acc[4][4];
#pragma unroll
    for (int i = 0; i < 4; i++)
#pragma unroll
        for (int j = 0; j < 4; j++) acc[i][j] = 0.f;

    for (int kb = 0; kb < DIM_IN; kb += 32) {
        // load A tile: 64 x 32 floats = 512 float4, 256 threads x 2
#pragma unroll
        for (int it = 0; it < 2; it++) {
            int i  = tid + it * 256;         // float4 index, 8 per row
            int r  = i >> 3;
            int c4 = i & 7;
            int gr = row0 + r;
            float4 v = make_float4(0.f, 0.f, 0.f, 0.f);
            if (gr < N_NODES)
                v = *(const float4*)&X[gr * DIM_IN + kb + c4 * 4];
            *(float4*)&As[r][c4 * 4] = v;    // 36*4=144B row stride, 16B aligned
        }
        // load B tile: 32 x 64 floats = 512 float4
#pragma unroll
        for (int it = 0; it < 2; it++) {
            int i  = tid + it * 256;
            int r  = i >> 4;                 // 16 float4 per row
            int c4 = i & 15;
            *(float4*)&Bs[r][c4 * 4] = *(const float4*)&Wh[(kb + r) * DIM_OUT + c4 * 4];
        }
        __syncthreads();

#pragma unroll
        for (int k = 0; k < 32; k++) {
            float a0 = As[ty * 4 + 0][k];
            float a1 = As[ty * 4 + 1][k];
            float a2 = As[ty * 4 + 2][k];
            float a3 = As[ty * 4 + 3][k];
            float4 b = *(const float4*)&Bs[k][tx * 4];
            acc[0][0] = fmaf(a0, b.x, acc[0][0]); acc[0][1] = fmaf(a0, b.y, acc[0][1]);
            acc[0][2] = fmaf(a0, b.z, acc[0][2]); acc[0][3] = fmaf(a0, b.w, acc[0][3]);
            acc[1][0] = fmaf(a1, b.x, acc[1][0]); acc[1][1] = fmaf(a1, b.y, acc[1][1]);
            acc[1][2] = fmaf(a1, b.z, acc[1][2]); acc[1][3] = fmaf(a1, b.w, acc[1][3]);
            acc[2][0] = fmaf(a2, b.x, acc[2][0]); acc[2][1] = fmaf(a2, b.y, acc[2][1]);
            acc[2][2] = fmaf(a2, b.z, acc[2][2]); acc[2][3] = fmaf(a2, b.w, acc[2][3]);
            acc[3][0] = fmaf(a3, b.x, acc[3][0]); acc[3][1] = fmaf(a3, b.y, acc[3][1]);
            acc[3][2] = fmaf(a3, b.z, acc[3][2]); acc[3][3] = fmaf(a3, b.w, acc[3][3]);
        }
        __syncthreads();
    }

#pragma unroll
    for (int i = 0; i < 4; i++) {
        int gr = row0 + ty * 4 + i;
        if (gr < N_NODES) {
            float4 st = make_float4(acc[i][0], acc[i][1], acc[i][2], acc[i][3]);
            *(float4*)&g_H[gr * H_COLS + h * DIM_OUT + tx * 4] = st;
        }
    }
}

// ---------------- s_i / s_j: one warp per (node, head) ---------------------
__global__ void __launch_bounds__(256) s_kernel(const float* __restrict__ a) {
    int w = (blockIdx.x * 256 + threadIdx.x) >> 5;
    if (w >= N_NODES * HEADS) return;
    int lane = threadIdx.x & 31;
    int n = w >> 2, h = w & 3;
    float2 hv = *(const float2*)&g_H[n * H_COLS + h * DIM_OUT + lane * 2];
    float2 ai = *(const float2*)&a[h * 2 * DIM_OUT + lane * 2];
    float2 aj = *(const float2*)&a[h * 2 * DIM_OUT + DIM_OUT + lane * 2];
    float si = hv.x * ai.x + hv.y * ai.y;
    float sj = hv.x * aj.x + hv.y * aj.y;
#pragma unroll
    for (int o = 16; o; o >>= 1) {
        si += __shfl_xor_sync(0xffffffffu, si, o);
        sj += __shfl_xor_sync(0xffffffffu, sj, o);
    }
    if (lane == 0) {
        g_si[n * HEADS + h] = si;
        g_sj[n * HEADS + h] = sj;
    }
}

// ---------------- CSR build ------------------------------------------------
__global__ void zero_counts_kernel() {
    int i = blockIdx.x * blockDim.x + threadIdx.x;
    if (i < N_NODES) g_counts[i] = 0;
}

__global__ void hist_kernel(const int* __restrict__ src) {
    int e = blockIdx.x * blockDim.x + threadIdx.x;
    if (e < N_EDGES) atomicAdd(&g_counts[src[e]], 1);
}

__global__ void __launch_bounds__(1024) scan_kernel() {
    const int CH = (N_NODES + 1023) / 1024;  // 49
    __shared__ int sh[1024];
    int t = threadIdx.x;
    int b = t * CH;
    int e = min(b + CH, N_NODES);
    int s = 0;
    for (int i = b; i < e; i++) s += g_counts[i];
    sh[t] = s;
    __syncthreads();
    for (int off = 1; off < 1024; off <<= 1) {
        int v = (t >= off) ? sh[t - off] : 0;
        __syncthreads();
        sh[t] += v;
        __syncthreads();
    }
    int run = sh[t] - s;   // exclusive prefix
    for (int i = b; i < e; i++) {
        g_row_ptr[i] = run;
        g_cursor[i]  = run;
        run += g_counts[i];
    }
    if (t == 0) g_row_ptr[N_NODES] = sh[1023];
}

__global__ void scatter_kernel(const int* __restrict__ src, const int* __restrict__ dst) {
    int e = blockIdx.x * blockDim.x + threadIdx.x;
    if (e < N_EDGES) {
        int s = src[e];
        int p = atomicAdd(&g_cursor[s], 1);
        g_dst_sorted[p] = dst[e];
    }
}

// ---------------- fused GAT aggregation: one warp per src node -------------
__device__ __forceinline__ float lrelu(float v) { return v > 0.f ? v : NEG_SLOPE * v; }

__global__ void __launch_bounds__(256) gat_kernel(float* __restrict__ out) {
    const unsigned FULL = 0xffffffffu;
    int n = blockIdx.x * 8 + (threadIdx.x >> 5);
    if (n >= N_NODES) return;
    int lane = threadIdx.x & 31;
    int hsel = lane >> 3;      // head owned by this lane's columns

    int start = g_row_ptr[n];
    int deg   = g_row_ptr[n + 1] - start;
    float4 si4 = *(const float4*)&g_si[n * HEADS];

    // pass 1: per-head max of lrelu(si + sj[dst])
    float m0 = -1e30f, m1 = -1e30f, m2 = -1e30f, m3 = -1e30f;
    for (int base = 0; base < deg; base += 32) {
        int e = base + lane;
        if (e < deg) {
            int d = g_dst_sorted[start + e];
            float4 sj4 = *(const float4*)&g_sj[d * HEADS];
            m0 = fmaxf(m0, lrelu(si4.x + sj4.x));
            m1 = fmaxf(m1, lrelu(si4.y + sj4.y));
            m2 = fmaxf(m2, lrelu(si4.z + sj4.z));
            m3 = fmaxf(m3, lrelu(si4.w + sj4.w));
        }
    }
#pragma unroll
    for (int o = 16; o; o >>= 1) {
        m0 = fmaxf(m0, __shfl_xor_sync(FULL, m0, o));
        m1 = fmaxf(m1, __shfl_xor_sync(FULL, m1, o));
        m2 = fmaxf(m2, __shfl_xor_sync(FULL, m2, o));
        m3 = fmaxf(m3, __shfl_xor_sync(FULL, m3, o));
    }

    // pass 2: accumulate ex * h[dst] and denominators
    float acc[8];
#pragma unroll
    for (int i = 0; i < 8; i++) acc[i] = 0.f;
    float d0 = 0.f, d1 = 0.f, d2 = 0.f, d3 = 0.f;

    for (int base = 0; base < deg; base += 32) {
        int e = base + lane;
        int dn = 0;
        float ex0 = 0.f, ex1 = 0.f, ex2 = 0.f, ex3 = 0.f;
        if (e < deg) {
            dn = g_dst_sorted[start + e];
            float4 sj4 = *(const float4*)&g_sj[dn * HEADS];
            ex0 = __expf(lrelu(si4.x + sj4.x) - m0); d0 += ex0;
            ex1 = __expf(lrelu(si4.y + sj4.y) - m1); d1 += ex1;
            ex2 = __expf(lrelu(si4.z + sj4.z) - m2); d2 += ex2;
            ex3 = __expf(lrelu(si4.w + sj4.w) - m3); d3 += ex3;
        }
        int cnt = min(32, deg - base);
        for (int j = 0; j < cnt; j++) {
            int dj   = __shfl_sync(FULL, dn, j);
            float e0 = __shfl_sync(FULL, ex0, j);
            float e1 = __shfl_sync(FULL, ex1, j);
            float e2 = __shfl_sync(FULL, ex2, j);
            float e3 = __shfl_sync(FULL, ex3, j);
            float exl = (hsel == 0) ? e0 : (hsel == 1) ? e1 : (hsel == 2) ? e2 : e3;
            const float4* hp = (const float4*)&g_H[dj * H_COLS + lane * 8];
            float4 v0 = hp[0];
            float4 v1 = hp[1];
            acc[0] = fmaf(exl, v0.x, acc[0]);
            acc[1] = fmaf(exl, v0.y, acc[1]);
            acc[2] = fmaf(exl, v0.z, acc[2]);
            acc[3] = fmaf(exl, v0.w, acc[3]);
            acc[4] = fmaf(exl, v1.x, acc[4]);
            acc[5] = fmaf(exl, v1.y, acc[5]);
            acc[6] = fmaf(exl, v1.z, acc[6]);
            acc[7] = fmaf(exl, v1.w, acc[7]);
        }
    }

    // reduce denominators across warp
#pragma unroll
    for (int o = 16; o; o >>= 1) {
        d0 += __shfl_xor_sync(FULL, d0, o);
        d1 += __shfl_xor_sync(FULL, d1, o);
        d2 += __shfl_xor_sync(FULL, d2, o);
        d3 += __shfl_xor_sync(FULL, d3, o);
    }
    float dh   = (hsel == 0) ? d0 : (hsel == 1) ? d1 : (hsel == 2) ? d2 : d3;
    float dinv = (dh > 0.f) ? (0.25f / dh) : 0.f;  // fold 1/denom and head-mean

    float r[8];
#pragma unroll
    for (int i = 0; i < 8; i++) {
        r[i] = acc[i] * dinv;
        r[i] += __shfl_xor_sync(FULL, r[i], 8);
        r[i] += __shfl_xor_sync(FULL, r[i], 16);
    }
    if (lane < 8) {
        float4 o0 = make_float4(r[0], r[1], r[2], r[3]);
        float4 o1 = make_float4(r[4], r[5], r[6], r[7]);
        *(float4*)&out[n * DIM_OUT + lane * 8 + 0] = o0;
        *(float4*)&out[n * DIM_OUT + lane * 8 + 4] = o1;
    }
}

// ---------------- launch ---------------------------------------------------
extern "C" void kernel_launch(void* const* d_in, const int* in_sizes, int n_in,
                              void* d_out, int out_size) {
    const float* x  = (const float*)d_in[0];
    const int*   ei = (const int*)d_in[1];
    const float* W  = (const float*)d_in[2];
    const float* a  = (const float*)d_in[3];
    float* out = (float*)d_out;

    const int* src = ei;             // edge_index[0]
    const int* dst = ei + N_EDGES;   // edge_index[1]

    dim3 gg((N_NODES + 63) / 64, HEADS);
    gemm_kernel<<<gg, 256>>>(x, W);
    s_kernel<<<(N_NODES * HEADS * 32 + 255) / 256, 256>>>(a);

    zero_counts_kernel<<<(N_NODES + 255) / 256, 256>>>();
    hist_kernel<<<(N_EDGES + 255) / 256, 256>>>(src);
    scan_kernel<<<1, 1024>>>();
    scatter_kernel<<<(N_EDGES + 255) / 256, 256>>>(src, dst);

    gat_kernel<<<(N_NODES + 7) / 8, 256>>>(out);
}

// round 5
// speedup vs baseline: 1.3621x; 1.3621x over previous
#include <cuda_runtime.h>
#include <cuda_fp16.h>
#include <cstdint>

#define N_NODES 50000
#define N_EDGES 800000
#define DIM_IN  128
#define DIM_OUT 64
#define HEADS   4
#define NEG_SLOPE 0.2f
#define H_COLS  (HEADS * DIM_OUT)   // 256

typedef unsigned int u32;

// ---------------- scratch (device globals) ---------------------------------
__device__ __align__(16) __half g_Hh[N_NODES * H_COLS];         // 25.6 MB fp16 h
__device__ __align__(16) __half g_Wt[HEADS * DIM_OUT * DIM_IN]; // W^T fp16 [h*64+o][128]
__device__ __align__(16) float g_si[N_NODES * HEADS];
__device__ __align__(16) float g_sj[N_NODES * HEADS];
__device__ int g_counts[N_NODES];
__device__ int g_row_ptr[N_NODES + 1];
__device__ int g_cursor[N_NODES];
__device__ int g_dst_sorted[N_EDGES];

__device__ __forceinline__ float lrelu(float v) { return v > 0.f ? v : NEG_SLOPE * v; }

// ---------------- prep: W transpose+fp16 convert, zero counts --------------
// blocks [0,128): convert W; blocks [128, ...): zero counts
__global__ void __launch_bounds__(256) prep_kernel(const float* __restrict__ W) {
    if (blockIdx.x < 128) {
        int idx = blockIdx.x * 256 + threadIdx.x;      // 32768 = HEADS*DIM_IN*DIM_OUT
        int h = idx >> 13;                             // /8192
        int r = idx & 8191;
        int o = r >> 7;                                // /128
        int d = r & 127;
        g_Wt[(h * DIM_OUT + o) * DIM_IN + d] =
            __float2half(W[h * DIM_IN * DIM_OUT + d * DIM_OUT + o]);
    } else {
        int i = (blockIdx.x - 128) * 256 + threadIdx.x;
        if (i < N_NODES) g_counts[i] = 0;
    }
}

// ---------------- tensor-core GEMM + fused s_i/s_j epilogue ----------------
// block = 256 thr = 8 warps = 2 m-groups(16 rows) x 4 heads. M-tile = 32 rows.
#define A_STRIDE 136   // halfs per row; 16B-aligned rows, conflict-spread
__global__ void __launch_bounds__(256) gemm_kernel(const float* __restrict__ X,
                                                   const float* __restrict__ a) {
    __shared__ __half As[32 * A_STRIDE];

    const int row0 = blockIdx.x * 32;
    const int tid  = threadIdx.x;

    // load + convert A tile (32x128 fp32 -> fp16 smem), 4 float4 per thread
#pragma unroll
    for (int t = 0; t < 4; t++) {
        int i4 = tid + t * 256;          // float4 idx, 32 per row
        int r  = i4 >> 5;
        int c4 = i4 & 31;
        int gr = row0 + r;
        float4 v = make_float4(0.f, 0.f, 0.f, 0.f);
        if (gr < N_NODES) v = *(const float4*)&X[gr * DIM_IN + c4 * 4];
        __half2 h01 = __floats2half2_rn(v.x, v.y);
        __half2 h23 = __floats2half2_rn(v.z, v.w);
        *(uint2*)&As[r * A_STRIDE + c4 * 4] =
            make_uint2(*(u32*)&h01, *(u32*)&h23);
    }
    __syncthreads();

    const int warp  = tid >> 5;
    const int lane  = tid & 31;
    const int gid   = lane >> 2;   // group id 0..7
    const int tg    = lane & 3;    // thread in group
    const int h     = warp & 3;
    const int mbase = (warp >> 2) * 16;

    float acc[8][4];
#pragma unroll
    for (int n = 0; n < 8; n++)
#pragma unroll
        for (int j = 0; j < 4; j++) acc[n][j] = 0.f;

    const __half* Bp = &g_Wt[(h * DIM_OUT) * DIM_IN];
    const int row_lo = mbase + gid;
    const int row_hi = row_lo + 8;

#pragma unroll
    for (int kc = 0; kc < 8; kc++) {
        int k0 = kc * 16 + tg * 2;
        u32 a0 = *(const u32*)&As[row_lo * A_STRIDE + k0];
        u32 a1 = *(const u32*)&As[row_hi * A_STRIDE + k0];
        u32 a2 = *(const u32*)&As[row_lo * A_STRIDE + k0 + 8];
        u32 a3 = *(const u32*)&As[row_hi * A_STRIDE + k0 + 8];
#pragma unroll
        for (int nt = 0; nt < 8; nt++) {
            int o = nt * 8 + gid;
            const __half* bp = Bp + o * DIM_IN + k0;
            u32 b0 = *(const u32*)(bp);
            u32 b1 = *(const u32*)(bp + 8);
            asm volatile(
                "mma.sync.aligned.m16n8k16.row.col.f32.f16.f16.f32 "
                "{%0,%1,%2,%3}, {%4,%5,%6,%7}, {%8,%9}, {%0,%1,%2,%3};"
                : "+f"(acc[nt][0]), "+f"(acc[nt][1]), "+f"(acc[nt][2]), "+f"(acc[nt][3])
                : "r"(a0), "r"(a1), "r"(a2), "r"(a3), "r"(b0), "r"(b1));
        }
    }

    // ---- epilogue: s_i/s_j partials from fp32 accs, fp16 H stores ----
    float si_lo = 0.f, sj_lo = 0.f, si_hi = 0.f, sj_hi = 0.f;
    const int node_lo = row0 + mbase + gid;
    const int node_hi = node_lo + 8;

#pragma unroll
    for (int nt = 0; nt < 8; nt++) {
        int o = nt * 8 + tg * 2;
        float ai0 = a[h * 2 * DIM_OUT + o];
        float ai1 = a[h * 2 * DIM_OUT + o + 1];
        float aj0 = a[h * 2 * DIM_OUT + DIM_OUT + o];
        float aj1 = a[h * 2 * DIM_OUT + DIM_OUT + o + 1];
        si_lo += acc[nt][0] * ai0 + acc[nt][1] * ai1;
        sj_lo += acc[nt][0] * aj0 + acc[nt][1] * aj1;
        si_hi += acc[nt][2] * ai0 + acc[nt][3] * ai1;
        sj_hi += acc[nt][2] * aj0 + acc[nt][3] * aj1;

        __half2 lo = __floats2half2_rn(acc[nt][0], acc[nt][1]);
        __half2 hi = __floats2half2_rn(acc[nt][2], acc[nt][3]);
        if (node_lo < N_NODES)
            *(u32*)&g_Hh[node_lo * H_COLS + h * DIM_OUT + o] = *(u32*)&lo;
        if (node_hi < N_NODES)
            *(u32*)&g_Hh[node_hi * H_COLS + h * DIM_OUT + o] = *(u32*)&hi;
    }
    // reduce over the 4 lanes of the group (cols)
#pragma unroll
    for (int off = 1; off <= 2; off <<= 1) {
        si_lo += __shfl_xor_sync(0xffffffffu, si_lo, off);
        sj_lo += __shfl_xor_sync(0xffffffffu, sj_lo, off);
        si_hi += __shfl_xor_sync(0xffffffffu, si_hi, off);
        sj_hi += __shfl_xor_sync(0xffffffffu, sj_hi, off);
    }
    if (tg == 0) {
        if (node_lo < N_NODES) {
            g_si[node_lo * HEADS + h] = si_lo;
            g_sj[node_lo * HEADS + h] = sj_lo;
        }
        if (node_hi < N_NODES) {
            g_si[node_hi * HEADS + h] = si_hi;
            g_sj[node_hi * HEADS + h] = sj_hi;
        }
    }
}

// ---------------- CSR build ------------------------------------------------
__global__ void hist_kernel(const int* __restrict__ src) {
    int i = blockIdx.x * blockDim.x + threadIdx.x;   // 200000 int4
    if (i < N_EDGES / 4) {
        int4 s = ((const int4*)src)[i];
        atomicAdd(&g_counts[s.x], 1);
        atomicAdd(&g_counts[s.y], 1);
        atomicAdd(&g_counts[s.z], 1);
        atomicAdd(&g_counts[s.w], 1);
    }
}

__global__ void __launch_bounds__(1024) scan_kernel() {
    const int CH = (N_NODES + 1023) / 1024;  // 49
    __shared__ int sh[1024];
    int t = threadIdx.x;
    int b = t * CH;
    int e = min(b + CH, N_NODES);
    int s = 0;
#pragma unroll 8
    for (int i = b; i < e; i++) s += g_counts[i];
    sh[t] = s;
    __syncthreads();
    for (int off = 1; off < 1024; off <<= 1) {
        int v = (t >= off) ? sh[t - off] : 0;
        __syncthreads();
        sh[t] += v;
        __syncthreads();
    }
    int run = sh[t] - s;   // exclusive prefix
    for (int i = b; i < e; i++) {
        g_row_ptr[i] = run;
        g_cursor[i]  = run;
        run += g_counts[i];
    }
    if (t == 0) g_row_ptr[N_NODES] = sh[1023];
}

__global__ void scatter_kernel(const int* __restrict__ src, const int* __restrict__ dst) {
    int i = blockIdx.x * blockDim.x + threadIdx.x;
    if (i < N_EDGES / 4) {
        int4 s = ((const int4*)src)[i];
        int4 d = ((const int4*)dst)[i];
        g_dst_sorted[atomicAdd(&g_cursor[s.x], 1)] = d.x;
        g_dst_sorted[atomicAdd(&g_cursor[s.y], 1)] = d.y;
        g_dst_sorted[atomicAdd(&g_cursor[s.z], 1)] = d.z;
        g_dst_sorted[atomicAdd(&g_cursor[s.w], 1)] = d.w;
    }
}

// ---------------- fused GAT aggregation: one warp per src node -------------
// No max-subtraction pass: scores are O(few), exp cannot overflow fp32 and
// softmax is shift-invariant.
__global__ void __launch_bounds__(256) gat_kernel(float* __restrict__ out) {
    const unsigned FULL = 0xffffffffu;
    __shared__ int   sd[8][32];
    __shared__ float se[8][32][4];

    int w = threadIdx.x >> 5;
    int n = blockIdx.x * 8 + w;
    if (n >= N_NODES) return;
    int lane = threadIdx.x & 31;
    int hsel = lane >> 3;      // head owned by this lane's 8 columns

    int start = g_row_ptr[n];
    int deg   = g_row_ptr[n + 1] - start;
    float4 si4 = *(const float4*)&g_si[n * HEADS];

    float acc[8];
#pragma unroll
    for (int i = 0; i < 8; i++) acc[i] = 0.f;
    float d0 = 0.f, d1 = 0.f, d2 = 0.f, d3 = 0.f;

    for (int base = 0; base < deg; base += 32) {
        int e = base + lane;
        int dn = 0;
        float ex0 = 0.f, ex1 = 0.f, ex2 = 0.f, ex3 = 0.f;
        if (e < deg) {
            dn = g_dst_sorted[start + e];
            float4 sj4 = *(const float4*)&g_sj[dn * HEADS];
            ex0 = __expf(lrelu(si4.x + sj4.x)); d0 += ex0;
            ex1 = __expf(lrelu(si4.y + sj4.y)); d1 += ex1;
            ex2 = __expf(lrelu(si4.z + sj4.z)); d2 += ex2;
            ex3 = __expf(lrelu(si4.w + sj4.w)); d3 += ex3;
        }
        sd[w][lane] = dn;
        *(float4*)&se[w][lane][0] = make_float4(ex0, ex1, ex2, ex3);
        __syncwarp();

        int cnt = min(32, deg - base);
        for (int j = 0; j < cnt; j++) {
            int   dj  = sd[w][j];
            float exl = se[w][j][hsel];
            uint4 v = *(const uint4*)&g_Hh[dj * H_COLS + lane * 8];
            float2 f0 = __half22float2(*(__half2*)&v.x);
            float2 f1 = __half22float2(*(__half2*)&v.y);
            float2 f2 = __half22float2(*(__half2*)&v.z);
            float2 f3 = __half22float2(*(__half2*)&v.w);
            acc[0] = fmaf(exl, f0.x, acc[0]);
            acc[1] = fmaf(exl, f0.y, acc[1]);
            acc[2] = fmaf(exl, f1.x, acc[2]);
            acc[3] = fmaf(exl, f1.y, acc[3]);
            acc[4] = fmaf(exl, f2.x, acc[4]);
            acc[5] = fmaf(exl, f2.y, acc[5]);
            acc[6] = fmaf(exl, f3.x, acc[6]);
            acc[7] = fmaf(exl, f3.y, acc[7]);
        }
        __syncwarp();
    }

    // reduce denominators across warp
#pragma unroll
    for (int o = 16; o; o >>= 1) {
        d0 += __shfl_xor_sync(FULL, d0, o);
        d1 += __shfl_xor_sync(FULL, d1, o);
        d2 += __shfl_xor_sync(FULL, d2, o);
        d3 += __shfl_xor_sync(FULL, d3, o);
    }
    float dh   = (hsel == 0) ? d0 : (hsel == 1) ? d1 : (hsel == 2) ? d2 : d3;
    float dinv = (dh > 0.f) ? (0.25f / dh) : 0.f;  // fold 1/denom and head-mean

    float r[8];
#pragma unroll
    for (int i = 0; i < 8; i++) {
        r[i] = acc[i] * dinv;
        r[i] += __shfl_xor_sync(FULL, r[i], 8);   // sum heads 0+1 / 2+3
        r[i] += __shfl_xor_sync(FULL, r[i], 16);  // sum all heads
    }
    if (lane < 8) {
        *(float4*)&out[n * DIM_OUT + lane * 8 + 0] = make_float4(r[0], r[1], r[2], r[3]);
        *(float4*)&out[n * DIM_OUT + lane * 8 + 4] = make_float4(r[4], r[5], r[6], r[7]);
    }
}

// ---------------- launch ---------------------------------------------------
extern "C" void kernel_launch(void* const* d_in, const int* in_sizes, int n_in,
                              void* d_out, int out_size) {
    const float* x  = (const float*)d_in[0];
    const int*   ei = (const int*)d_in[1];
    const float* W  = (const float*)d_in[2];
    const float* a  = (const float*)d_in[3];
    float* out = (float*)d_out;

    const int* src = ei;             // edge_index[0]
    const int* dst = ei + N_EDGES;   // edge_index[1]

    prep_kernel<<<128 + (N_NODES + 255) / 256, 256>>>(W);
    gemm_kernel<<<(N_NODES + 31) / 32, 256>>>(x, a);

    hist_kernel<<<(N_EDGES / 4 + 255) / 256, 256>>>(src);
    scan_kernel<<<1, 1024>>>();
    scatter_kernel<<<(N_EDGES / 4 + 255) / 256, 256>>>(src, dst);

    gat_kernel<<<(N_NODES + 7) / 8, 256>>>(out);
}

// round 6
// speedup vs baseline: 1.9429x; 1.4265x over previous
#include <cuda_runtime.h>
#include <cuda_fp16.h>
#include <cstdint>

#define N_NODES 50000
#define N_EDGES 800000
#define DIM_IN  128
#define DIM_OUT 64
#define HEADS   4
#define NEG_SLOPE 0.2f
#define H_COLS  (HEADS * DIM_OUT)   // 256

#define SCAN_BLOCKS ((N_NODES + 255) / 256)   // 196

typedef unsigned int u32;

// ---------------- scratch (device globals) ---------------------------------
__device__ __align__(16) __half g_Hh[N_NODES * H_COLS];         // 25.6 MB fp16 h
__device__ __align__(16) __half g_Wt[HEADS * DIM_OUT * DIM_IN]; // W^T fp16 [h*64+o][128]
__device__ __align__(16) float g_si[N_NODES * HEADS];
__device__ __align__(16) float g_sj[N_NODES * HEADS];
__device__ int g_counts[N_NODES];
__device__ int g_prescan[SCAN_BLOCKS * 256];
__device__ int g_bsums[SCAN_BLOCKS];
__device__ int g_boff[SCAN_BLOCKS];
__device__ int g_row_ptr[N_NODES + 1];
__device__ int g_cursor[N_NODES];
__device__ int g_dst_sorted[N_EDGES];

__device__ __forceinline__ float lrelu(float v) { return v > 0.f ? v : NEG_SLOPE * v; }

// ---------------- prep: W transpose+fp16 convert, zero counts --------------
__global__ void __launch_bounds__(256) prep_kernel(const float* __restrict__ W) {
    if (blockIdx.x < 128) {
        int idx = blockIdx.x * 256 + threadIdx.x;      // 32768 = HEADS*DIM_IN*DIM_OUT
        int h = idx >> 13;
        int r = idx & 8191;
        int o = r >> 7;
        int d = r & 127;
        g_Wt[(h * DIM_OUT + o) * DIM_IN + d] =
            __float2half(W[h * DIM_IN * DIM_OUT + d * DIM_OUT + o]);
    } else {
        int i = (blockIdx.x - 128) * 256 + threadIdx.x;
        if (i < N_NODES) g_counts[i] = 0;
    }
}

// ---------------- tensor-core GEMM + fused s_i/s_j epilogue ----------------
#define A_STRIDE 136
__global__ void __launch_bounds__(256) gemm_kernel(const float* __restrict__ X,
                                                   const float* __restrict__ a) {
    __shared__ __half As[32 * A_STRIDE];

    const int row0 = blockIdx.x * 32;
    const int tid  = threadIdx.x;

#pragma unroll
    for (int t = 0; t < 4; t++) {
        int i4 = tid + t * 256;
        int r  = i4 >> 5;
        int c4 = i4 & 31;
        int gr = row0 + r;
        float4 v = make_float4(0.f, 0.f, 0.f, 0.f);
        if (gr < N_NODES) v = *(const float4*)&X[gr * DIM_IN + c4 * 4];
        __half2 h01 = __floats2half2_rn(v.x, v.y);
        __half2 h23 = __floats2half2_rn(v.z, v.w);
        *(uint2*)&As[r * A_STRIDE + c4 * 4] =
            make_uint2(*(u32*)&h01, *(u32*)&h23);
    }
    __syncthreads();

    const int warp  = tid >> 5;
    const int lane  = tid & 31;
    const int gid   = lane >> 2;
    const int tg    = lane & 3;
    const int h     = warp & 3;
    const int mbase = (warp >> 2) * 16;

    float acc[8][4];
#pragma unroll
    for (int n = 0; n < 8; n++)
#pragma unroll
        for (int j = 0; j < 4; j++) acc[n][j] = 0.f;

    const __half* Bp = &g_Wt[(h * DIM_OUT) * DIM_IN];
    const int row_lo = mbase + gid;
    const int row_hi = row_lo + 8;

#pragma unroll
    for (int kc = 0; kc < 8; kc++) {
        int k0 = kc * 16 + tg * 2;
        u32 a0 = *(const u32*)&As[row_lo * A_STRIDE + k0];
        u32 a1 = *(const u32*)&As[row_hi * A_STRIDE + k0];
        u32 a2 = *(const u32*)&As[row_lo * A_STRIDE + k0 + 8];
        u32 a3 = *(const u32*)&As[row_hi * A_STRIDE + k0 + 8];
#pragma unroll
        for (int nt = 0; nt < 8; nt++) {
            int o = nt * 8 + gid;
            const __half* bp = Bp + o * DIM_IN + k0;
            u32 b0 = *(const u32*)(bp);
            u32 b1 = *(const u32*)(bp + 8);
            asm volatile(
                "mma.sync.aligned.m16n8k16.row.col.f32.f16.f16.f32 "
                "{%0,%1,%2,%3}, {%4,%5,%6,%7}, {%8,%9}, {%0,%1,%2,%3};"
                : "+f"(acc[nt][0]), "+f"(acc[nt][1]), "+f"(acc[nt][2]), "+f"(acc[nt][3])
                : "r"(a0), "r"(a1), "r"(a2), "r"(a3), "r"(b0), "r"(b1));
        }
    }

    float si_lo = 0.f, sj_lo = 0.f, si_hi = 0.f, sj_hi = 0.f;
    const int node_lo = row0 + mbase + gid;
    const int node_hi = node_lo + 8;

#pragma unroll
    for (int nt = 0; nt < 8; nt++) {
        int o = nt * 8 + tg * 2;
        float ai0 = a[h * 2 * DIM_OUT + o];
        float ai1 = a[h * 2 * DIM_OUT + o + 1];
        float aj0 = a[h * 2 * DIM_OUT + DIM_OUT + o];
        float aj1 = a[h * 2 * DIM_OUT + DIM_OUT + o + 1];
        si_lo += acc[nt][0] * ai0 + acc[nt][1] * ai1;
        sj_lo += acc[nt][0] * aj0 + acc[nt][1] * aj1;
        si_hi += acc[nt][2] * ai0 + acc[nt][3] * ai1;
        sj_hi += acc[nt][2] * aj0 + acc[nt][3] * aj1;

        __half2 lo = __floats2half2_rn(acc[nt][0], acc[nt][1]);
        __half2 hi = __floats2half2_rn(acc[nt][2], acc[nt][3]);
        if (node_lo < N_NODES)
            *(u32*)&g_Hh[node_lo * H_COLS + h * DIM_OUT + o] = *(u32*)&lo;
        if (node_hi < N_NODES)
            *(u32*)&g_Hh[node_hi * H_COLS + h * DIM_OUT + o] = *(u32*)&hi;
    }
#pragma unroll
    for (int off = 1; off <= 2; off <<= 1) {
        si_lo += __shfl_xor_sync(0xffffffffu, si_lo, off);
        sj_lo += __shfl_xor_sync(0xffffffffu, sj_lo, off);
        si_hi += __shfl_xor_sync(0xffffffffu, si_hi, off);
        sj_hi += __shfl_xor_sync(0xffffffffu, sj_hi, off);
    }
    if (tg == 0) {
        if (node_lo < N_NODES) {
            g_si[node_lo * HEADS + h] = si_lo;
            g_sj[node_lo * HEADS + h] = sj_lo;
        }
        if (node_hi < N_NODES) {
            g_si[node_hi * HEADS + h] = si_hi;
            g_sj[node_hi * HEADS + h] = sj_hi;
        }
    }
}

// ---------------- CSR build ------------------------------------------------
__global__ void hist_kernel(const int* __restrict__ src) {
    int i = blockIdx.x * blockDim.x + threadIdx.x;
    if (i < N_EDGES / 4) {
        int4 s = ((const int4*)src)[i];
        atomicAdd(&g_counts[s.x], 1);
        atomicAdd(&g_counts[s.y], 1);
        atomicAdd(&g_counts[s.z], 1);
        atomicAdd(&g_counts[s.w], 1);
    }
}

// scan phase A: per-block inclusive scan over 256 counts -> exclusive prescan + block sum
__global__ void __launch_bounds__(256) scanA_kernel() {
    __shared__ int sh[256];
    int t = threadIdx.x;
    int i = blockIdx.x * 256 + t;
    int c = (i < N_NODES) ? g_counts[i] : 0;
    sh[t] = c;
    __syncthreads();
#pragma unroll
    for (int off = 1; off < 256; off <<= 1) {
        int v = (t >= off) ? sh[t - off] : 0;
        __syncthreads();
        sh[t] += v;
        __syncthreads();
    }
    g_prescan[i] = sh[t] - c;          // exclusive within block
    if (t == 255) g_bsums[blockIdx.x] = sh[255];
}

// scan phase B: single block scans the 196 block sums (exclusive)
__global__ void __launch_bounds__(256) scanB_kernel() {
    __shared__ int sh[256];
    int t = threadIdx.x;
    int v = (t < SCAN_BLOCKS) ? g_bsums[t] : 0;
    sh[t] = v;
    __syncthreads();
#pragma unroll
    for (int off = 1; off < 256; off <<= 1) {
        int u = (t >= off) ? sh[t - off] : 0;
        __syncthreads();
        sh[t] += u;
        __syncthreads();
    }
    if (t < SCAN_BLOCKS) g_boff[t] = sh[t] - v;   // exclusive
    if (t == 255) g_row_ptr[N_NODES] = sh[255];   // = total = N_EDGES
}

// scan phase C: expand
__global__ void __launch_bounds__(256) scanC_kernel() {
    int i = blockIdx.x * 256 + threadIdx.x;
    if (i < N_NODES) {
        int v = g_prescan[i] + g_boff[blockIdx.x];
        g_row_ptr[i] = v;
        g_cursor[i]  = v;
    }
}

__global__ void scatter_kernel(const int* __restrict__ src, const int* __restrict__ dst) {
    int i = blockIdx.x * blockDim.x + threadIdx.x;
    if (i < N_EDGES / 4) {
        int4 s = ((const int4*)src)[i];
        int4 d = ((const int4*)dst)[i];
        g_dst_sorted[atomicAdd(&g_cursor[s.x], 1)] = d.x;
        g_dst_sorted[atomicAdd(&g_cursor[s.y], 1)] = d.y;
        g_dst_sorted[atomicAdd(&g_cursor[s.z], 1)] = d.z;
        g_dst_sorted[atomicAdd(&g_cursor[s.w], 1)] = d.w;
    }
}

// ---------------- fused GAT aggregation: one warp per src node -------------
__global__ void __launch_bounds__(256) gat_kernel(float* __restrict__ out) {
    const unsigned FULL = 0xffffffffu;
    __shared__ int   sd[8][32];
    __shared__ float se[8][32][4];

    int w = threadIdx.x >> 5;
    int n = blockIdx.x * 8 + w;
    if (n >= N_NODES) return;
    int lane = threadIdx.x & 31;
    int hsel = lane >> 3;

    int start = g_row_ptr[n];
    int deg   = g_row_ptr[n + 1] - start;
    float4 si4 = *(const float4*)&g_si[n * HEADS];

    float acc[8];
#pragma unroll
    for (int i = 0; i < 8; i++) acc[i] = 0.f;
    float d0 = 0.f, d1 = 0.f, d2 = 0.f, d3 = 0.f;

    for (int base = 0; base < deg; base += 32) {
        int e = base + lane;
        int dn = 0;
        float ex0 = 0.f, ex1 = 0.f, ex2 = 0.f, ex3 = 0.f;
        if (e < deg) {
            dn = g_dst_sorted[start + e];
            float4 sj4 = *(const float4*)&g_sj[dn * HEADS];
            ex0 = __expf(lrelu(si4.x + sj4.x)); d0 += ex0;
            ex1 = __expf(lrelu(si4.y + sj4.y)); d1 += ex1;
            ex2 = __expf(lrelu(si4.z + sj4.z)); d2 += ex2;
            ex3 = __expf(lrelu(si4.w + sj4.w)); d3 += ex3;
        }
        sd[w][lane] = dn;
        *(float4*)&se[w][lane][0] = make_float4(ex0, ex1, ex2, ex3);
        __syncwarp();

        int cnt = min(32, deg - base);
        for (int j = 0; j < cnt; j++) {
            int   dj  = sd[w][j];
            float exl = se[w][j][hsel];
            uint4 v = *(const uint4*)&g_Hh[dj * H_COLS + lane * 8];
            float2 f0 = __half22float2(*(__half2*)&v.x);
            float2 f1 = __half22float2(*(__half2*)&v.y);
            float2 f2 = __half22float2(*(__half2*)&v.z);
            float2 f3 = __half22float2(*(__half2*)&v.w);
            acc[0] = fmaf(exl, f0.x, acc[0]);
            acc[1] = fmaf(exl, f0.y, acc[1]);
            acc[2] = fmaf(exl, f1.x, acc[2]);
            acc[3] = fmaf(exl, f1.y, acc[3]);
            acc[4] = fmaf(exl, f2.x, acc[4]);
            acc[5] = fmaf(exl, f2.y, acc[5]);
            acc[6] = fmaf(exl, f3.x, acc[6]);
            acc[7] = fmaf(exl, f3.y, acc[7]);
        }
        __syncwarp();
    }

#pragma unroll
    for (int o = 16; o; o >>= 1) {
        d0 += __shfl_xor_sync(FULL, d0, o);
        d1 += __shfl_xor_sync(FULL, d1, o);
        d2 += __shfl_xor_sync(FULL, d2, o);
        d3 += __shfl_xor_sync(FULL, d3, o);
    }
    float dh   = (hsel == 0) ? d0 : (hsel == 1) ? d1 : (hsel == 2) ? d2 : d3;
    float dinv = (dh > 0.f) ? (0.25f / dh) : 0.f;

    float r[8];
#pragma unroll
    for (int i = 0; i < 8; i++) {
        r[i] = acc[i] * dinv;
        r[i] += __shfl_xor_sync(FULL, r[i], 8);
        r[i] += __shfl_xor_sync(FULL, r[i], 16);
    }
    if (lane < 8) {
        *(float4*)&out[n * DIM_OUT + lane * 8 + 0] = make_float4(r[0], r[1], r[2], r[3]);
        *(float4*)&out[n * DIM_OUT + lane * 8 + 4] = make_float4(r[4], r[5], r[6], r[7]);
    }
}

// ---------------- launch ---------------------------------------------------
extern "C" void kernel_launch(void* const* d_in, const int* in_sizes, int n_in,
                              void* d_out, int out_size) {
    const float* x  = (const float*)d_in[0];
    const int*   ei = (const int*)d_in[1];
    const float* W  = (const float*)d_in[2];
    const float* a  = (const float*)d_in[3];
    float* out = (float*)d_out;

    const int* src = ei;
    const int* dst = ei + N_EDGES;

    prep_kernel<<<128 + (N_NODES + 255) / 256, 256>>>(W);
    gemm_kernel<<<(N_NODES + 31) / 32, 256>>>(x, a);

    hist_kernel<<<(N_EDGES / 4 + 255) / 256, 256>>>(src);
    scanA_kernel<<<SCAN_BLOCKS, 256>>>();
    scanB_kernel<<<1, 256>>>();
    scanC_kernel<<<SCAN_BLOCKS, 256>>>();
    scatter_kernel<<<(N_EDGES / 4 + 255) / 256, 256>>>(src, dst);

    gat_kernel<<<(N_NODES + 7) / 8, 256>>>(out);
}